// round 12
// baseline (speedup 1.0000x reference)
#include <cuda_runtime.h>
#include <cuda_fp16.h>
#include <cstdint>

#define NN 50000
#define NE 800000
#define D 256
#define DOUT 128
#define SCAN_B 49   // ceil(50000/1024)

// ---------------- device scratch (static: no allocation allowed) ----------------
__device__ unsigned short g_x16[NN * D];     // fp16 activations
__device__ unsigned short g_h0[NN * D];
__device__ unsigned short g_h1[NN * D];
__device__ unsigned short g_agg[NN * D];     // agg / z buffer
__device__ unsigned short g_wt[8 * 65536];   // transposed fp16 weights
__device__ float g_deginv[NN];
__device__ int   g_deg[NN];
__device__ int   g_rowptr[NN + 1];
__device__ int   g_cursor[NN];
__device__ int   g_col[NE];
__device__ int   g_bsum[SCAN_B];
__device__ int   g_is64;

// ids: 0 -> x, 1 -> h0, 2 -> h1, 3 -> agg/z
__device__ __forceinline__ unsigned short* bufp(int id) {
    if (id == 0) return g_x16;
    if (id == 1) return g_h0;
    if (id == 2) return g_h1;
    return g_agg;
}

__device__ __forceinline__ int edge_at(const void* ei, int word) {
    if (g_is64) return (int)((const long long*)ei)[word];
    return ((const int*)ei)[word];
}

__device__ __forceinline__ uint32_t smem_u32(const void* p) {
    uint32_t a;
    asm("{ .reg .u64 t; cvta.to.shared.u64 t, %1; cvt.u32.u64 %0, t; }" : "=r"(a) : "l"(p));
    return a;
}
__device__ __forceinline__ void ldm4(uint32_t addr, uint32_t& r0, uint32_t& r1,
                                     uint32_t& r2, uint32_t& r3) {
    asm volatile("ldmatrix.sync.aligned.m8n8.x4.shared.b16 {%0,%1,%2,%3}, [%4];"
                 : "=r"(r0), "=r"(r1), "=r"(r2), "=r"(r3) : "r"(addr));
}
__device__ __forceinline__ void mma16816(float* c, const uint32_t* a, const uint32_t* b) {
    asm volatile("mma.sync.aligned.m16n8k16.row.col.f32.f16.f16.f32 "
                 "{%0,%1,%2,%3}, {%4,%5,%6,%7}, {%8,%9}, {%0,%1,%2,%3};"
                 : "+f"(c[0]), "+f"(c[1]), "+f"(c[2]), "+f"(c[3])
                 : "r"(a[0]), "r"(a[1]), "r"(a[2]), "r"(a[3]), "r"(b[0]), "r"(b[1]));
}
__device__ __forceinline__ void cpa16(uint32_t dst, const void* src, int valid) {
    asm volatile("cp.async.cg.shared.global [%0], [%1], 16, %2;"
                 :: "r"(dst), "l"(src), "r"(valid ? 16 : 0));
}
#define CP_COMMIT() asm volatile("cp.async.commit_group;" ::: "memory")
#define CP_WAIT1()  asm volatile("cp.async.wait_group 1;" ::: "memory")
#define CP_WAIT0()  asm volatile("cp.async.wait_group 0;" ::: "memory")

// ---------------- prep: x -> fp16 AND all weights transposed fp16, one kernel ----------------
#define NPREPX (NN * D / 4)           // 3.2M (x, 4 elems/thread)
__global__ void k_prep(const float* __restrict__ x,
                       const float* __restrict__ wl, const float* __restrict__ wr,
                       const float* __restrict__ w1, const float* __restrict__ w2) {
    int idx = blockIdx.x * blockDim.x + threadIdx.x;
    if (idx < NPREPX) {
        int i = idx * 4;
#pragma unroll
        for (int j = 0; j < 4; j++)
            g_x16[i + j] = __half_as_ushort(__float2half_rn(x[i + j]));
    } else if (idx < NPREPX + 7 * 65536) {
        int q = idx - NPREPX;
        int m = q >> 16, t = q & 65535;
        const float* src = (m < 3) ? (wl + (size_t)m * 65536)
                         : (m < 6) ? (wr + (size_t)(m - 3) * 65536) : w1;
        int k = t >> 8, n = t & 255;
        g_wt[m * 65536 + n * 256 + k] = __half_as_ushort(__float2half_rn(src[t]));
    } else if (idx < NPREPX + 7 * 65536 + D * DOUT) {
        int t = idx - NPREPX - 7 * 65536;
        int k = t >> 7, n = t & 127;
        g_wt[7 * 65536 + n * 256 + k] = __half_as_ushort(__float2half_rn(w2[t]));
    }
}

// ---------------- zero degrees + dtype probe (block 0) ----------------
__global__ void k_zero(const int* __restrict__ ei32) {
    int i = blockIdx.x * blockDim.x + threadIdx.x;
    if (i < NN) g_deg[i] = 0;
    if (blockIdx.x == 0) {
        __shared__ int nz;
        if (threadIdx.x == 0) nz = 0;
        __syncthreads();
        if (ei32[2 * threadIdx.x + 1] != 0) atomicOr(&nz, 1);
        __syncthreads();
        if (threadIdx.x == 0) g_is64 = nz ? 0 : 1;
    }
}

// ---------------- CSR build ----------------
__global__ void k_hist(const void* __restrict__ ei) {
    int e = blockIdx.x * blockDim.x + threadIdx.x;
    if (e < NE) {
        unsigned d = (unsigned)edge_at(ei, NE + e);
        if (d < NN) atomicAdd(&g_deg[d], 1);
    }
}
__global__ void k_scan1() {
    __shared__ int s[1024];
    int t = threadIdx.x;
    int i = blockIdx.x * 1024 + t;
    int v = (i < NN) ? g_deg[i] : 0;
    s[t] = v;
    __syncthreads();
    for (int o = 1; o < 1024; o <<= 1) {
        int a = (t >= o) ? s[t - o] : 0;
        __syncthreads();
        s[t] += a;
        __syncthreads();
    }
    if (i < NN) g_rowptr[i] = s[t] - v;
    if (t == 1023) g_bsum[blockIdx.x] = s[1023];
}
__global__ void k_scan2() {
    int run = 0;
    for (int b = 0; b < SCAN_B; b++) { int t = g_bsum[b]; g_bsum[b] = run; run += t; }
}
__global__ void k_scan3() {
    int i = blockIdx.x * blockDim.x + threadIdx.x;
    if (i < NN) {
        int rp = g_rowptr[i] + g_bsum[i >> 10];
        g_rowptr[i] = rp;
        g_cursor[i] = rp;
        int dg = g_deg[i];
        g_deginv[i] = 1.0f / (float)(dg > 0 ? dg : 1);
    }
    if (i == 0) g_rowptr[NN] = NE;
}
__global__ void k_fill(const void* __restrict__ ei) {
    int e = blockIdx.x * blockDim.x + threadIdx.x;
    if (e < NE) {
        unsigned d = (unsigned)edge_at(ei, NE + e);
        unsigned s = (unsigned)edge_at(ei, e);
        if (d < NN && s < NN) {
            int pos = atomicAdd(&g_cursor[d], 1);
            g_col[pos] = (int)s;
        }
    }
}

// ---------------- mean aggregation (fp16 half2, no smem/syncs, MLP-4) ----------------
// All 128 threads walk the same (ascending) index list; index loads are
// warp-uniform broadcasts, feature gathers are fully coalesced 512 B rows.
__global__ void k_agg(int src_id) {
    const unsigned int* __restrict__ H = (const unsigned int*)bufp(src_id);  // 128 uints/row
    unsigned int* __restrict__ O = (unsigned int*)g_agg;
    int t = threadIdx.x;   // 0..127
    for (int r = blockIdx.x; r < NN; r += gridDim.x) {
        int beg = g_rowptr[r], end = g_rowptr[r + 1];
        float a0 = 0.f, a1 = 0.f;
        int e = beg;
        for (; e + 4 <= end; e += 4) {
            int i0 = __ldg(g_col + e);
            int i1 = __ldg(g_col + e + 1);
            int i2 = __ldg(g_col + e + 2);
            int i3 = __ldg(g_col + e + 3);
            unsigned int v0 = H[(size_t)i0 * 128 + t];
            unsigned int v1 = H[(size_t)i1 * 128 + t];
            unsigned int v2 = H[(size_t)i2 * 128 + t];
            unsigned int v3 = H[(size_t)i3 * 128 + t];
            float2 f0 = __half22float2(*reinterpret_cast<__half2*>(&v0));
            float2 f1 = __half22float2(*reinterpret_cast<__half2*>(&v1));
            float2 f2 = __half22float2(*reinterpret_cast<__half2*>(&v2));
            float2 f3 = __half22float2(*reinterpret_cast<__half2*>(&v3));
            a0 += (f0.x + f1.x) + (f2.x + f3.x);
            a1 += (f0.y + f1.y) + (f2.y + f3.y);
        }
        for (; e < end; e++) {
            unsigned int v = H[(size_t)__ldg(g_col + e) * 128 + t];
            float2 f = __half22float2(*reinterpret_cast<__half2*>(&v));
            a0 += f.x;
            a1 += f.y;
        }
        float di = g_deginv[r];
        __half2 o = __floats2half2_rn(a0 * di, a1 * di);
        O[(size_t)r * 128 + t] = *reinterpret_cast<unsigned int*>(&o);
    }
}

// ---------------- fp16 tensor-core GEMM, 2-stage cp.async, K-chunk 32 ----------------
// C[128x128 tile] = sum_src A@B^T, fused bias(+relu).
// Tiles A/B: 128 rows x 32 fp16, 80 B padded rows (conflict-free ldmatrix).
#define TROWB   80
#define TILE_B  (128 * TROWB)       // 10240
#define STAGE_B (2 * TILE_B)        // 20480
#define SMEM_DYN (2 * STAGE_B)      // 40960 (40 KB)

__global__ __launch_bounds__(256, 2)
void k_mma(int a1id, int a2id, int dual, int outp,
           float* __restrict__ cext, int woff1, int woff2,
           const float* __restrict__ bias, int relu, int ldc) {
    extern __shared__ __align__(16) unsigned char sT[];
    uint32_t sb = smem_u32(sT);
    int tid = threadIdx.x;
    int lane = tid & 31;
    int wid = tid >> 5;
    int wm = wid & 1;        // 2 warp-rows (64 rows)
    int wn = wid >> 1;       // 4 warp-cols (32 cols)
    int bm = blockIdx.x * 128;
    int bn = blockIdx.y * 128;

    const unsigned short* pA[2] = { bufp(a1id), bufp(a2id) };
    const unsigned short* pB[2] = { g_wt + woff1, g_wt + woff2 };

    float acc[16][4];
#pragma unroll
    for (int i = 0; i < 16; i++)
#pragma unroll
        for (int j = 0; j < 4; j++) acc[i][j] = 0.f;

    // loader: 128 rows x 32 fp16 (64 B) per tile; thread -> (row, 16B segment pair)
    int lrow = tid >> 1, s0 = tid & 1;
    int gr = bm + lrow;
    int av = gr < NN;
    size_t arow = (size_t)(av ? gr : 0) * D;
    size_t brow = (size_t)(bn + lrow) * D;
    uint32_t drow = sb + (uint32_t)(lrow * TROWB);

    // ldmatrix lane-address components (proven mapping, stride 80)
    int grp = lane >> 3, lr = lane & 7;
    int a_r = wm * 64 + ((grp & 1) << 3) + lr;
    int a_c = (grp & 2) ? 8 : 0;
    int b_r = wn * 32 + ((grp & 2) << 2) + lr;
    int b_c = (grp & 1) << 3;
    uint32_t offA = (uint32_t)(a_r * TROWB + a_c * 2);
    uint32_t offB = (uint32_t)(b_r * TROWB + b_c * 2);

    int NIT = dual ? 16 : 8;

    // prologue: iteration 0 -> stage 0
#pragma unroll
    for (int j2 = 0; j2 < 2; j2++) {
        int seg = s0 + 2 * j2;
        uint32_t d = drow + (uint32_t)(seg * 16);
        size_t go = (size_t)(seg * 8);
        cpa16(d,          pA[0] + arow + go, av);
        cpa16(d + TILE_B, pB[0] + brow + go, 1);
    }
    CP_COMMIT();

    for (int it = 0; it < NIT; it++) {
        if (it + 1 < NIT) {
            int s = (it + 1) >> 3, kc = (it + 1) & 7;
            uint32_t stg = (uint32_t)(((it + 1) & 1) * STAGE_B);
#pragma unroll
            for (int j2 = 0; j2 < 2; j2++) {
                int seg = s0 + 2 * j2;
                uint32_t d = drow + stg + (uint32_t)(seg * 16);
                size_t go = (size_t)(kc * 32 + seg * 8);
                cpa16(d,          pA[s] + arow + go, av);
                cpa16(d + TILE_B, pB[s] + brow + go, 1);
            }
            CP_COMMIT();
            CP_WAIT1();
        } else {
            CP_WAIT0();
        }
        __syncthreads();

        uint32_t base = sb + (uint32_t)((it & 1) * STAGE_B);
#pragma unroll
        for (int kk = 0; kk < 32; kk += 16) {
            uint32_t koff = (uint32_t)(kk * 2);
            uint32_t b[4][2];
#pragma unroll
            for (int nb = 0; nb < 2; nb++) {
                uint32_t off = offB + koff + (uint32_t)(nb * 16 * TROWB);
                uint32_t t0, t1, t2, t3;
                ldm4(base + TILE_B + off, t0, t1, t2, t3);
                b[nb * 2][0] = t0; b[nb * 2][1] = t1;
                b[nb * 2 + 1][0] = t2; b[nb * 2 + 1][1] = t3;
            }
            uint32_t a[4];
#pragma unroll
            for (int mi = 0; mi < 4; mi++) {
                uint32_t off = offA + koff + (uint32_t)(mi * 16 * TROWB);
                ldm4(base + off, a[0], a[1], a[2], a[3]);
#pragma unroll
                for (int nj = 0; nj < 4; nj++)
                    mma16816(acc[mi * 4 + nj], a, b[nj]);
            }
        }
        __syncthreads();   // protect the stage being prefetched next iteration
    }

    // epilogue
    unsigned short* oH = (outp >= 0) ? bufp(outp) : nullptr;
#pragma unroll
    for (int mi = 0; mi < 4; mi++) {
#pragma unroll
        for (int nj = 0; nj < 4; nj++) {
            float* c = acc[mi * 4 + nj];
            int col = bn + wn * 32 + nj * 8 + (lane & 3) * 2;
            float bi0 = bias[col], bi1 = bias[col + 1];
#pragma unroll
            for (int half = 0; half < 2; half++) {
                int r = bm + wm * 64 + mi * 16 + (lane >> 2) + half * 8;
                if (r >= NN) continue;
                float v0 = c[half * 2] + bi0;
                float v1 = c[half * 2 + 1] + bi1;
                if (relu) { v0 = fmaxf(v0, 0.f); v1 = fmaxf(v1, 0.f); }
                if (oH) {
                    *(ushort2*)(oH + (size_t)r * D + col) = make_ushort2(
                        __half_as_ushort(__float2half_rn(v0)),
                        __half_as_ushort(__float2half_rn(v1)));
                } else {
                    *(float2*)(cext + (size_t)r * ldc + col) = make_float2(v0, v1);
                }
            }
        }
    }
}

// ---------------- row-wise log_softmax over 128 cols, 2 rows/block ----------------
__global__ void k_lsm(float* __restrict__ out) {
    int r = blockIdx.x * 2 + (threadIdx.x >> 7);
    int t = threadIdx.x & 127;
    if (r >= NN) return;
    float v = out[(size_t)r * DOUT + t];
    __shared__ float smax[2][4], ssum[2][4];
    int g = threadIdx.x >> 7;
    float m = v;
#pragma unroll
    for (int o = 16; o; o >>= 1) m = fmaxf(m, __shfl_xor_sync(0xffffffffu, m, o));
    if ((t & 31) == 0) smax[g][t >> 5] = m;
    __syncthreads();
    float mm = fmaxf(fmaxf(smax[g][0], smax[g][1]), fmaxf(smax[g][2], smax[g][3]));
    float e = expf(v - mm);
    float sum = e;
#pragma unroll
    for (int o = 16; o; o >>= 1) sum += __shfl_xor_sync(0xffffffffu, sum, o);
    if ((t & 31) == 0) ssum[g][t >> 5] = sum;
    __syncthreads();
    float tot = ssum[g][0] + ssum[g][1] + ssum[g][2] + ssum[g][3];
    out[(size_t)r * DOUT + t] = v - mm - logf(tot);
}

// ---------------- launch: kernel launches ONLY ----------------
extern "C" void kernel_launch(void* const* d_in, const int* in_sizes, int n_in,
                              void* d_out, int out_size) {
    const float* x  = (const float*)d_in[0];
    const void*  ei = d_in[1];
    const float* wl = (const float*)d_in[2];
    const float* bl = (const float*)d_in[3];
    const float* wr = (const float*)d_in[4];
    const float* w1 = (const float*)d_in[5];
    const float* b1 = (const float*)d_in[6];
    const float* w2 = (const float*)d_in[7];
    const float* b2 = (const float*)d_in[8];
    float* out = (float*)d_out;

    cudaFuncSetAttribute(k_mma, cudaFuncAttributeMaxDynamicSharedMemorySize, SMEM_DYN);

    // operand prep + CSR by dst
    k_prep<<<(NPREPX + 7 * 65536 + D * DOUT + 255) / 256, 256>>>(x, wl, wr, w1, w2);
    k_zero<<<(NN + 255) / 256, 256>>>((const int*)ei);
    k_hist<<<(NE + 255) / 256, 256>>>(ei);
    k_scan1<<<SCAN_B, 1024>>>();
    k_scan2<<<1, 1>>>();
    k_scan3<<<(NN + 255) / 256, 256>>>();
    k_fill<<<(NE + 255) / 256, 256>>>(ei);

    dim3 g2((NN + 127) / 128, 2);
    dim3 g1((NN + 127) / 128, 1);

    // layer 0: agg(x); h0 = relu(agg@wl0 + x@wr0 + bl0)
    k_agg<<<6144, 128>>>(0);
    k_mma<<<g2, 256, SMEM_DYN>>>(3, 0, 1, 1, nullptr, 0 * 65536, 3 * 65536, bl + 0 * D, 1, D);
    // layer 1: agg(h0); h1 = relu(...)
    k_agg<<<6144, 128>>>(1);
    k_mma<<<g2, 256, SMEM_DYN>>>(3, 1, 1, 2, nullptr, 1 * 65536, 4 * 65536, bl + 1 * D, 1, D);
    // layer 2: agg(h1); h0 = relu(...)
    k_agg<<<6144, 128>>>(2);
    k_mma<<<g2, 256, SMEM_DYN>>>(3, 2, 1, 1, nullptr, 2 * 65536, 5 * 65536, bl + 2 * D, 1, D);
    // post_mp: z = h0@w1 + b1 ; out = z@w2 + b2
    k_mma<<<g2, 256, SMEM_DYN>>>(1, 1, 0, 3, nullptr, 6 * 65536, 0, b1, 0, D);
    k_mma<<<g1, 256, SMEM_DYN>>>(3, 3, 0, -1, out, 7 * 65536, 0, b2, 0, DOUT);
    k_lsm<<<(NN + 1) / 2, 256>>>(out);
}

// round 13
// speedup vs baseline: 1.1367x; 1.1367x over previous
#include <cuda_runtime.h>
#include <cuda_fp16.h>
#include <cstdint>

#define NN 50000
#define NE 800000
#define D 256
#define DOUT 128
#define SCAN_B 49   // ceil(50000/1024)

// ---------------- device scratch (static: no allocation allowed) ----------------
__device__ unsigned short g_x16[NN * D];     // fp16 activations
__device__ unsigned short g_h0[NN * D];
__device__ unsigned short g_h1[NN * D];
__device__ unsigned short g_agg[NN * D];     // agg buffer
__device__ unsigned short g_wt[8 * 65536];   // transposed fp16 weights
__device__ float g_deginv[NN];
__device__ int   g_deg[NN];
__device__ int   g_rowptr[NN + 1];
__device__ int   g_cursor[NN];
__device__ int   g_col[NE];
__device__ int   g_bsum[SCAN_B];
__device__ int   g_is64;

// ids: 0 -> x, 1 -> h0, 2 -> h1, 3 -> agg
__device__ __forceinline__ unsigned short* bufp(int id) {
    if (id == 0) return g_x16;
    if (id == 1) return g_h0;
    if (id == 2) return g_h1;
    return g_agg;
}

__device__ __forceinline__ int edge_at(const void* ei, int word) {
    if (g_is64) return (int)((const long long*)ei)[word];
    return ((const int*)ei)[word];
}

__device__ __forceinline__ uint32_t smem_u32(const void* p) {
    uint32_t a;
    asm("{ .reg .u64 t; cvta.to.shared.u64 t, %1; cvt.u32.u64 %0, t; }" : "=r"(a) : "l"(p));
    return a;
}
__device__ __forceinline__ void ldm4(uint32_t addr, uint32_t& r0, uint32_t& r1,
                                     uint32_t& r2, uint32_t& r3) {
    asm volatile("ldmatrix.sync.aligned.m8n8.x4.shared.b16 {%0,%1,%2,%3}, [%4];"
                 : "=r"(r0), "=r"(r1), "=r"(r2), "=r"(r3) : "r"(addr));
}
__device__ __forceinline__ void mma16816(float* c, const uint32_t* a, const uint32_t* b) {
    asm volatile("mma.sync.aligned.m16n8k16.row.col.f32.f16.f16.f32 "
                 "{%0,%1,%2,%3}, {%4,%5,%6,%7}, {%8,%9}, {%0,%1,%2,%3};"
                 : "+f"(c[0]), "+f"(c[1]), "+f"(c[2]), "+f"(c[3])
                 : "r"(a[0]), "r"(a[1]), "r"(a[2]), "r"(a[3]), "r"(b[0]), "r"(b[1]));
}
__device__ __forceinline__ void cpa16(uint32_t dst, const void* src, int valid) {
    asm volatile("cp.async.cg.shared.global [%0], [%1], 16, %2;"
                 :: "r"(dst), "l"(src), "r"(valid ? 16 : 0));
}
#define CP_COMMIT() asm volatile("cp.async.commit_group;" ::: "memory")
#define CP_WAIT1()  asm volatile("cp.async.wait_group 1;" ::: "memory")
#define CP_WAIT0()  asm volatile("cp.async.wait_group 0;" ::: "memory")

// ---------------- prep: x -> fp16 AND all weights transposed fp16, one kernel ----------------
#define NPREPX (NN * D / 4)
__global__ void k_prep(const float* __restrict__ x,
                       const float* __restrict__ wl, const float* __restrict__ wr,
                       const float* __restrict__ w1, const float* __restrict__ w2) {
    int idx = blockIdx.x * blockDim.x + threadIdx.x;
    if (idx < NPREPX) {
        int i = idx * 4;
#pragma unroll
        for (int j = 0; j < 4; j++)
            g_x16[i + j] = __half_as_ushort(__float2half_rn(x[i + j]));
    } else if (idx < NPREPX + 7 * 65536) {
        int q = idx - NPREPX;
        int m = q >> 16, t = q & 65535;
        const float* src = (m < 3) ? (wl + (size_t)m * 65536)
                         : (m < 6) ? (wr + (size_t)(m - 3) * 65536) : w1;
        int k = t >> 8, n = t & 255;
        g_wt[m * 65536 + n * 256 + k] = __half_as_ushort(__float2half_rn(src[t]));
    } else if (idx < NPREPX + 7 * 65536 + D * DOUT) {
        int t = idx - NPREPX - 7 * 65536;
        int k = t >> 7, n = t & 127;
        g_wt[7 * 65536 + n * 256 + k] = __half_as_ushort(__float2half_rn(w2[t]));
    }
}

// ---------------- zero degrees + dtype probe (block 0) ----------------
__global__ void k_zero(const int* __restrict__ ei32) {
    int i = blockIdx.x * blockDim.x + threadIdx.x;
    if (i < NN) g_deg[i] = 0;
    if (blockIdx.x == 0) {
        __shared__ int nz;
        if (threadIdx.x == 0) nz = 0;
        __syncthreads();
        if (ei32[2 * threadIdx.x + 1] != 0) atomicOr(&nz, 1);
        __syncthreads();
        if (threadIdx.x == 0) g_is64 = nz ? 0 : 1;
    }
}

// ---------------- CSR build ----------------
__global__ void k_hist(const void* __restrict__ ei) {
    int e = blockIdx.x * blockDim.x + threadIdx.x;
    if (e < NE) {
        unsigned d = (unsigned)edge_at(ei, NE + e);
        if (d < NN) atomicAdd(&g_deg[d], 1);
    }
}
__global__ void k_scan1() {
    __shared__ int s[1024];
    int t = threadIdx.x;
    int i = blockIdx.x * 1024 + t;
    int v = (i < NN) ? g_deg[i] : 0;
    s[t] = v;
    __syncthreads();
    for (int o = 1; o < 1024; o <<= 1) {
        int a = (t >= o) ? s[t - o] : 0;
        __syncthreads();
        s[t] += a;
        __syncthreads();
    }
    if (i < NN) g_rowptr[i] = s[t] - v;
    if (t == 1023) g_bsum[blockIdx.x] = s[1023];
}
__global__ void k_scan2() {
    int run = 0;
    for (int b = 0; b < SCAN_B; b++) { int t = g_bsum[b]; g_bsum[b] = run; run += t; }
}
__global__ void k_scan3() {
    int i = blockIdx.x * blockDim.x + threadIdx.x;
    if (i < NN) {
        int rp = g_rowptr[i] + g_bsum[i >> 10];
        g_rowptr[i] = rp;
        g_cursor[i] = rp;
        int dg = g_deg[i];
        g_deginv[i] = 1.0f / (float)(dg > 0 ? dg : 1);
    }
    if (i == 0) g_rowptr[NN] = NE;
}
__global__ void k_fill(const void* __restrict__ ei) {
    int e = blockIdx.x * blockDim.x + threadIdx.x;
    if (e < NE) {
        unsigned d = (unsigned)edge_at(ei, NE + e);
        unsigned s = (unsigned)edge_at(ei, e);
        if (d < NN && s < NN) {
            int pos = atomicAdd(&g_cursor[d], 1);
            g_col[pos] = (int)s;
        }
    }
}

// ---------------- mean aggregation (fp16 half2, smem-staged indices) ----------------
__global__ void k_agg(int src_id) {
    const unsigned int* __restrict__ H = (const unsigned int*)bufp(src_id);
    unsigned int* __restrict__ O = (unsigned int*)g_agg;
    __shared__ int sc[128];
    int t = threadIdx.x;
    for (int r = blockIdx.x; r < NN; r += gridDim.x) {
        int beg = g_rowptr[r], end = g_rowptr[r + 1];
        float a0 = 0.f, a1 = 0.f;
        for (int base = beg; base < end; base += 128) {
            int cnt = min(128, end - base);
            __syncthreads();
            if (t < cnt) sc[t] = g_col[base + t];
            __syncthreads();
            int i = 0;
            for (; i + 4 <= cnt; i += 4) {
                unsigned int v0 = H[(size_t)sc[i]     * 128 + t];
                unsigned int v1 = H[(size_t)sc[i + 1] * 128 + t];
                unsigned int v2 = H[(size_t)sc[i + 2] * 128 + t];
                unsigned int v3 = H[(size_t)sc[i + 3] * 128 + t];
                float2 f0 = __half22float2(*reinterpret_cast<__half2*>(&v0));
                float2 f1 = __half22float2(*reinterpret_cast<__half2*>(&v1));
                float2 f2 = __half22float2(*reinterpret_cast<__half2*>(&v2));
                float2 f3 = __half22float2(*reinterpret_cast<__half2*>(&v3));
                a0 += (f0.x + f1.x) + (f2.x + f3.x);
                a1 += (f0.y + f1.y) + (f2.y + f3.y);
            }
            for (; i < cnt; i++) {
                unsigned int v = H[(size_t)sc[i] * 128 + t];
                float2 f = __half22float2(*reinterpret_cast<__half2*>(&v));
                a0 += f.x;
                a1 += f.y;
            }
        }
        float di = g_deginv[r];
        __half2 o = __floats2half2_rn(a0 * di, a1 * di);
        O[(size_t)r * 128 + t] = *reinterpret_cast<unsigned int*>(&o);
    }
}

// ---------------- fp16 tensor-core GEMM (layers), 2-stage cp.async, K-chunk 32 ----------------
#define TROWB   80
#define TILE_B  (128 * TROWB)       // 10240
#define STAGE_B (2 * TILE_B)        // 20480
#define SMEM_DYN (2 * STAGE_B)      // 40960

__global__ __launch_bounds__(256, 2)
void k_mma(int a1id, int a2id, int outp, int woff1, int woff2,
           const float* __restrict__ bias) {
    extern __shared__ __align__(16) unsigned char sT[];
    uint32_t sb = smem_u32(sT);
    int tid = threadIdx.x;
    int lane = tid & 31;
    int wid = tid >> 5;
    int wm = wid & 1;
    int wn = wid >> 1;
    int bm = blockIdx.x * 128;
    int bn = blockIdx.y * 128;

    const unsigned short* pA[2] = { bufp(a1id), bufp(a2id) };
    const unsigned short* pB[2] = { g_wt + woff1, g_wt + woff2 };

    float acc[16][4];
#pragma unroll
    for (int i = 0; i < 16; i++)
#pragma unroll
        for (int j = 0; j < 4; j++) acc[i][j] = 0.f;

    int lrow = tid >> 1, s0 = tid & 1;
    int gr = bm + lrow;
    int av = gr < NN;
    size_t arow = (size_t)(av ? gr : 0) * D;
    size_t brow = (size_t)(bn + lrow) * D;
    uint32_t drow = sb + (uint32_t)(lrow * TROWB);

    int grp = lane >> 3, lr = lane & 7;
    int a_r = wm * 64 + ((grp & 1) << 3) + lr;
    int a_c = (grp & 2) ? 8 : 0;
    int b_r = wn * 32 + ((grp & 2) << 2) + lr;
    int b_c = (grp & 1) << 3;
    uint32_t offA = (uint32_t)(a_r * TROWB + a_c * 2);
    uint32_t offB = (uint32_t)(b_r * TROWB + b_c * 2);

    const int NIT = 16;   // dual source, 8 K-chunks each

#pragma unroll
    for (int j2 = 0; j2 < 2; j2++) {
        int seg = s0 + 2 * j2;
        uint32_t d = drow + (uint32_t)(seg * 16);
        size_t go = (size_t)(seg * 8);
        cpa16(d,          pA[0] + arow + go, av);
        cpa16(d + TILE_B, pB[0] + brow + go, 1);
    }
    CP_COMMIT();

    for (int it = 0; it < NIT; it++) {
        if (it + 1 < NIT) {
            int s = (it + 1) >> 3, kc = (it + 1) & 7;
            uint32_t stg = (uint32_t)(((it + 1) & 1) * STAGE_B);
#pragma unroll
            for (int j2 = 0; j2 < 2; j2++) {
                int seg = s0 + 2 * j2;
                uint32_t d = drow + stg + (uint32_t)(seg * 16);
                size_t go = (size_t)(kc * 32 + seg * 8);
                cpa16(d,          pA[s] + arow + go, av);
                cpa16(d + TILE_B, pB[s] + brow + go, 1);
            }
            CP_COMMIT();
            CP_WAIT1();
        } else {
            CP_WAIT0();
        }
        __syncthreads();

        uint32_t base = sb + (uint32_t)((it & 1) * STAGE_B);
#pragma unroll
        for (int kk = 0; kk < 32; kk += 16) {
            uint32_t koff = (uint32_t)(kk * 2);
            uint32_t b[4][2];
#pragma unroll
            for (int nb = 0; nb < 2; nb++) {
                uint32_t off = offB + koff + (uint32_t)(nb * 16 * TROWB);
                uint32_t t0, t1, t2, t3;
                ldm4(base + TILE_B + off, t0, t1, t2, t3);
                b[nb * 2][0] = t0; b[nb * 2][1] = t1;
                b[nb * 2 + 1][0] = t2; b[nb * 2 + 1][1] = t3;
            }
            uint32_t a[4];
#pragma unroll
            for (int mi = 0; mi < 4; mi++) {
                uint32_t off = offA + koff + (uint32_t)(mi * 16 * TROWB);
                ldm4(base + off, a[0], a[1], a[2], a[3]);
#pragma unroll
                for (int nj = 0; nj < 4; nj++)
                    mma16816(acc[mi * 4 + nj], a, b[nj]);
            }
        }
        __syncthreads();
    }

    unsigned short* oH = bufp(outp);
#pragma unroll
    for (int mi = 0; mi < 4; mi++) {
#pragma unroll
        for (int nj = 0; nj < 4; nj++) {
            float* c = acc[mi * 4 + nj];
            int col = bn + wn * 32 + nj * 8 + (lane & 3) * 2;
            float bi0 = bias[col], bi1 = bias[col + 1];
#pragma unroll
            for (int half = 0; half < 2; half++) {
                int r = bm + wm * 64 + mi * 16 + (lane >> 2) + half * 8;
                if (r >= NN) continue;
                float v0 = fmaxf(c[half * 2] + bi0, 0.f);
                float v1 = fmaxf(c[half * 2 + 1] + bi1, 0.f);
                *(ushort2*)(oH + (size_t)r * D + col) = make_ushort2(
                    __half_as_ushort(__float2half_rn(v0)),
                    __half_as_ushort(__float2half_rn(v1)));
            }
        }
    }
}

// ---------------- fused post-MLP: out = log_softmax((h0@w1+b1)@w2+b2) ----------------
// z tile [128 x 256] fp16 in smem, row stride 528 B (132 words == 4 mod 32:
// 8-row ldmatrix tiles cover all 32 banks -> conflict-free).
#define ZROWB 528
#define Z_OFF SMEM_DYN                       // 40960
#define SMEM_POST (Z_OFF + 128 * ZROWB)      // 40960 + 67584 = 108544

__global__ __launch_bounds__(256, 2)
void k_post(float* __restrict__ out, const float* __restrict__ b1v,
            const float* __restrict__ b2v) {
    extern __shared__ __align__(16) unsigned char sT[];
    uint32_t sb = smem_u32(sT);
    uint32_t zb = sb + Z_OFF;
    int tid = threadIdx.x, lane = tid & 31, wid = tid >> 5;
    int wm = wid & 1, wn = wid >> 1;
    int bm = blockIdx.x * 128;

    const unsigned short* A1 = g_h0;
    const unsigned short* B1 = g_wt + 6 * 65536;
    const unsigned short* B2 = g_wt + 7 * 65536;

    int lrow = tid >> 1, s0 = tid & 1;
    int gr = bm + lrow;
    int av = gr < NN;
    size_t arow = (size_t)(av ? gr : 0) * D;
    uint32_t drow = sb + (uint32_t)(lrow * TROWB);

    int grp = lane >> 3, lr = lane & 7;
    int a_r = wm * 64 + ((grp & 1) << 3) + lr;
    int a_c = (grp & 2) ? 8 : 0;
    int b_r = wn * 32 + ((grp & 2) << 2) + lr;
    int b_c = (grp & 1) << 3;
    uint32_t offA = (uint32_t)(a_r * TROWB + a_c * 2);
    uint32_t offB = (uint32_t)(b_r * TROWB + b_c * 2);

    // ---- GEMM1: z[128 x 256] = h0 @ w1T + b1 (two 128-col passes)
    for (int pn = 0; pn < 2; pn++) {
        int bn = pn * 128;
        size_t brow = (size_t)(bn + lrow) * D;
        float acc[16][4];
#pragma unroll
        for (int i = 0; i < 16; i++)
#pragma unroll
            for (int j = 0; j < 4; j++) acc[i][j] = 0.f;

#pragma unroll
        for (int j2 = 0; j2 < 2; j2++) {
            int seg = s0 + 2 * j2;
            uint32_t d = drow + (uint32_t)(seg * 16);
            size_t go = (size_t)(seg * 8);
            cpa16(d,          A1 + arow + go, av);
            cpa16(d + TILE_B, B1 + brow + go, 1);
        }
        CP_COMMIT();

        for (int it = 0; it < 8; it++) {
            if (it + 1 < 8) {
                int kc = it + 1;
                uint32_t stg = (uint32_t)(((it + 1) & 1) * STAGE_B);
#pragma unroll
                for (int j2 = 0; j2 < 2; j2++) {
                    int seg = s0 + 2 * j2;
                    uint32_t d = drow + stg + (uint32_t)(seg * 16);
                    size_t go = (size_t)(kc * 32 + seg * 8);
                    cpa16(d,          A1 + arow + go, av);
                    cpa16(d + TILE_B, B1 + brow + go, 1);
                }
                CP_COMMIT();
                CP_WAIT1();
            } else {
                CP_WAIT0();
            }
            __syncthreads();

            uint32_t base = sb + (uint32_t)((it & 1) * STAGE_B);
#pragma unroll
            for (int kk = 0; kk < 32; kk += 16) {
                uint32_t koff = (uint32_t)(kk * 2);
                uint32_t b[4][2];
#pragma unroll
                for (int nb = 0; nb < 2; nb++) {
                    uint32_t off = offB + koff + (uint32_t)(nb * 16 * TROWB);
                    uint32_t t0, t1, t2, t3;
                    ldm4(base + TILE_B + off, t0, t1, t2, t3);
                    b[nb * 2][0] = t0; b[nb * 2][1] = t1;
                    b[nb * 2 + 1][0] = t2; b[nb * 2 + 1][1] = t3;
                }
                uint32_t a[4];
#pragma unroll
                for (int mi = 0; mi < 4; mi++) {
                    uint32_t off = offA + koff + (uint32_t)(mi * 16 * TROWB);
                    ldm4(base + off, a[0], a[1], a[2], a[3]);
#pragma unroll
                    for (int nj = 0; nj < 4; nj++)
                        mma16816(acc[mi * 4 + nj], a, b[nj]);
                }
            }
            __syncthreads();
        }

        // epilogue -> z smem (fp16, +b1, no relu)
#pragma unroll
        for (int mi = 0; mi < 4; mi++) {
#pragma unroll
            for (int nj = 0; nj < 4; nj++) {
                float* c = acc[mi * 4 + nj];
                int col = bn + wn * 32 + nj * 8 + (lane & 3) * 2;
                float bi0 = b1v[col], bi1 = b1v[col + 1];
#pragma unroll
                for (int half = 0; half < 2; half++) {
                    int rl = wm * 64 + mi * 16 + (lane >> 2) + half * 8;
                    __half2 o = __floats2half2_rn(c[half * 2] + bi0,
                                                  c[half * 2 + 1] + bi1);
                    *(__half2*)(sT + Z_OFF + rl * ZROWB + col * 2) = o;
                }
            }
        }
    }
    __syncthreads();   // z complete

    // ---- GEMM2: o[128 x 128] = z @ w2T (+b2 later)
    float acc[16][4];
#pragma unroll
    for (int i = 0; i < 16; i++)
#pragma unroll
        for (int j = 0; j < 4; j++) acc[i][j] = 0.f;

    size_t brow2 = (size_t)lrow * D;
#pragma unroll
    for (int j2 = 0; j2 < 2; j2++) {
        int seg = s0 + 2 * j2;
        cpa16(drow + (uint32_t)(seg * 16), B2 + brow2 + (size_t)(seg * 8), 1);
    }
    CP_COMMIT();

    uint32_t offA2 = (uint32_t)(a_r * ZROWB + a_c * 2);
    for (int it = 0; it < 8; it++) {
        if (it + 1 < 8) {
            int kc = it + 1;
            uint32_t stg = (uint32_t)(((it + 1) & 1) * STAGE_B);
#pragma unroll
            for (int j2 = 0; j2 < 2; j2++) {
                int seg = s0 + 2 * j2;
                cpa16(drow + stg + (uint32_t)(seg * 16),
                      B2 + brow2 + (size_t)(kc * 32 + seg * 8), 1);
            }
            CP_COMMIT();
            CP_WAIT1();
        } else {
            CP_WAIT0();
        }
        __syncthreads();

        uint32_t base = sb + (uint32_t)((it & 1) * STAGE_B);
#pragma unroll
        for (int kk = 0; kk < 32; kk += 16) {
            uint32_t b[4][2];
#pragma unroll
            for (int nb = 0; nb < 2; nb++) {
                uint32_t off = offB + (uint32_t)(kk * 2) + (uint32_t)(nb * 16 * TROWB);
                uint32_t t0, t1, t2, t3;
                ldm4(base + off, t0, t1, t2, t3);
                b[nb * 2][0] = t0; b[nb * 2][1] = t1;
                b[nb * 2 + 1][0] = t2; b[nb * 2 + 1][1] = t3;
            }
            uint32_t a[4];
#pragma unroll
            for (int mi = 0; mi < 4; mi++) {
                uint32_t off = zb + offA2 + (uint32_t)((it * 32 + kk) * 2)
                             + (uint32_t)(mi * 16 * ZROWB) - zb + zb;  // = zb + ...
                ldm4(off, a[0], a[1], a[2], a[3]);
#pragma unroll
                for (int nj = 0; nj < 4; nj++)
                    mma16816(acc[mi * 4 + nj], a, b[nj]);
            }
        }
        __syncthreads();
    }

    // ---- bias + log_softmax over the block's full 128-col rows
    // add b2
#pragma unroll
    for (int nj = 0; nj < 4; nj++) {
        int col = wn * 32 + nj * 8 + (lane & 3) * 2;
        float bi0 = b2v[col], bi1 = b2v[col + 1];
#pragma unroll
        for (int mi = 0; mi < 4; mi++) {
            acc[mi * 4 + nj][0] += bi0; acc[mi * 4 + nj][1] += bi1;
            acc[mi * 4 + nj][2] += bi0; acc[mi * 4 + nj][3] += bi1;
        }
    }

    float* redm = (float*)sT;          // 128 rows x 4 wn
    float* reds = (float*)sT + 512;
    // per-row max -> quad shfl -> smem partials
#pragma unroll
    for (int mi = 0; mi < 4; mi++)
#pragma unroll
        for (int half = 0; half < 2; half++) {
            float m = -3.4e38f;
#pragma unroll
            for (int nj = 0; nj < 4; nj++) {
                m = fmaxf(m, acc[mi * 4 + nj][half * 2]);
                m = fmaxf(m, acc[mi * 4 + nj][half * 2 + 1]);
            }
            m = fmaxf(m, __shfl_xor_sync(0xffffffffu, m, 1));
            m = fmaxf(m, __shfl_xor_sync(0xffffffffu, m, 2));
            int rl = wm * 64 + mi * 16 + (lane >> 2) + half * 8;
            if ((lane & 3) == 0) redm[rl * 4 + wn] = m;
        }
    __syncthreads();
    float mm8[8];
#pragma unroll
    for (int mi = 0; mi < 4; mi++)
#pragma unroll
        for (int half = 0; half < 2; half++) {
            int rl = wm * 64 + mi * 16 + (lane >> 2) + half * 8;
            mm8[mi * 2 + half] = fmaxf(fmaxf(redm[rl * 4], redm[rl * 4 + 1]),
                                       fmaxf(redm[rl * 4 + 2], redm[rl * 4 + 3]));
        }
    // per-row sum of exp
#pragma unroll
    for (int mi = 0; mi < 4; mi++)
#pragma unroll
        for (int half = 0; half < 2; half++) {
            float mm = mm8[mi * 2 + half];
            float s = 0.f;
#pragma unroll
            for (int nj = 0; nj < 4; nj++) {
                s += expf(acc[mi * 4 + nj][half * 2] - mm);
                s += expf(acc[mi * 4 + nj][half * 2 + 1] - mm);
            }
            s += __shfl_xor_sync(0xffffffffu, s, 1);
            s += __shfl_xor_sync(0xffffffffu, s, 2);
            int rl = wm * 64 + mi * 16 + (lane >> 2) + half * 8;
            if ((lane & 3) == 0) reds[rl * 4 + wn] = s;
        }
    __syncthreads();
    // final: out = v - mm - log(total)
#pragma unroll
    for (int mi = 0; mi < 4; mi++)
#pragma unroll
        for (int half = 0; half < 2; half++) {
            int rl = wm * 64 + mi * 16 + (lane >> 2) + half * 8;
            int r = bm + rl;
            if (r >= NN) continue;
            float tot = reds[rl * 4] + reds[rl * 4 + 1] + reds[rl * 4 + 2] + reds[rl * 4 + 3];
            float sub = mm8[mi * 2 + half] + logf(tot);
#pragma unroll
            for (int nj = 0; nj < 4; nj++) {
                int col = wn * 32 + nj * 8 + (lane & 3) * 2;
                float2 v = make_float2(acc[mi * 4 + nj][half * 2] - sub,
                                       acc[mi * 4 + nj][half * 2 + 1] - sub);
                *(float2*)(out + (size_t)r * DOUT + col) = v;
            }
        }
}

// ---------------- launch: kernel launches ONLY ----------------
extern "C" void kernel_launch(void* const* d_in, const int* in_sizes, int n_in,
                              void* d_out, int out_size) {
    const float* x  = (const float*)d_in[0];
    const void*  ei = d_in[1];
    const float* wl = (const float*)d_in[2];
    const float* bl = (const float*)d_in[3];
    const float* wr = (const float*)d_in[4];
    const float* w1 = (const float*)d_in[5];
    const float* b1 = (const float*)d_in[6];
    const float* w2 = (const float*)d_in[7];
    const float* b2 = (const float*)d_in[8];
    float* out = (float*)d_out;

    cudaFuncSetAttribute(k_mma,  cudaFuncAttributeMaxDynamicSharedMemorySize, SMEM_DYN);
    cudaFuncSetAttribute(k_post, cudaFuncAttributeMaxDynamicSharedMemorySize, SMEM_POST);

    // operand prep + CSR by dst
    k_prep<<<(NPREPX + 7 * 65536 + D * DOUT + 255) / 256, 256>>>(x, wl, wr, w1, w2);
    k_zero<<<(NN + 255) / 256, 256>>>((const int*)ei);
    k_hist<<<(NE + 255) / 256, 256>>>(ei);
    k_scan1<<<SCAN_B, 1024>>>();
    k_scan2<<<1, 1>>>();
    k_scan3<<<(NN + 255) / 256, 256>>>();
    k_fill<<<(NE + 255) / 256, 256>>>(ei);

    dim3 g2((NN + 127) / 128, 2);

    // layer 0: agg(x); h0 = relu(agg@wl0 + x@wr0 + bl0)
    k_agg<<<6144, 128>>>(0);
    k_mma<<<g2, 256, SMEM_DYN>>>(3, 0, 1, 0 * 65536, 3 * 65536, bl + 0 * D);
    // layer 1: agg(h0); h1 = relu(...)
    k_agg<<<6144, 128>>>(1);
    k_mma<<<g2, 256, SMEM_DYN>>>(3, 1, 2, 1 * 65536, 4 * 65536, bl + 1 * D);
    // layer 2: agg(h1); h0 = relu(...)
    k_agg<<<6144, 128>>>(2);
    k_mma<<<g2, 256, SMEM_DYN>>>(3, 2, 1, 2 * 65536, 5 * 65536, bl + 2 * D);
    // fused post_mp + log_softmax
    k_post<<<(NN + 127) / 128, 256, SMEM_POST>>>(out, b1, b2);
}

// round 14
// speedup vs baseline: 1.1552x; 1.0163x over previous
#include <cuda_runtime.h>
#include <cuda_fp16.h>
#include <cstdint>

#define NN 50000
#define NE 800000
#define D 256
#define DOUT 128
#define SCAN_B 49   // ceil(50000/1024)

// ---------------- device scratch (static: no allocation allowed) ----------------
__device__ unsigned short g_x16[NN * D];     // fp16 activations
__device__ unsigned short g_h0[NN * D];
__device__ unsigned short g_h1[NN * D];
__device__ unsigned short g_agg[NN * D];     // agg buffer
__device__ unsigned short g_wt[8 * 65536];   // transposed fp16 weights
__device__ float g_deginv[NN];
__device__ int   g_deg[NN];
__device__ int   g_rowptr[NN + 1];
__device__ int   g_cursor[NN];
__device__ int   g_col[NE];
__device__ int   g_bsum[SCAN_B];
__device__ int   g_is64;

// ids: 0 -> x, 1 -> h0, 2 -> h1, 3 -> agg
__device__ __forceinline__ unsigned short* bufp(int id) {
    if (id == 0) return g_x16;
    if (id == 1) return g_h0;
    if (id == 2) return g_h1;
    return g_agg;
}

__device__ __forceinline__ int edge_at(const void* ei, int word) {
    if (g_is64) return (int)((const long long*)ei)[word];
    return ((const int*)ei)[word];
}

__device__ __forceinline__ uint32_t smem_u32(const void* p) {
    uint32_t a;
    asm("{ .reg .u64 t; cvta.to.shared.u64 t, %1; cvt.u32.u64 %0, t; }" : "=r"(a) : "l"(p));
    return a;
}
__device__ __forceinline__ void ldm4(uint32_t addr, uint32_t& r0, uint32_t& r1,
                                     uint32_t& r2, uint32_t& r3) {
    asm volatile("ldmatrix.sync.aligned.m8n8.x4.shared.b16 {%0,%1,%2,%3}, [%4];"
                 : "=r"(r0), "=r"(r1), "=r"(r2), "=r"(r3) : "r"(addr));
}
__device__ __forceinline__ void mma16816(float* c, const uint32_t* a, const uint32_t* b) {
    asm volatile("mma.sync.aligned.m16n8k16.row.col.f32.f16.f16.f32 "
                 "{%0,%1,%2,%3}, {%4,%5,%6,%7}, {%8,%9}, {%0,%1,%2,%3};"
                 : "+f"(c[0]), "+f"(c[1]), "+f"(c[2]), "+f"(c[3])
                 : "r"(a[0]), "r"(a[1]), "r"(a[2]), "r"(a[3]), "r"(b[0]), "r"(b[1]));
}
__device__ __forceinline__ void cpa16(uint32_t dst, const void* src, int valid) {
    asm volatile("cp.async.cg.shared.global [%0], [%1], 16, %2;"
                 :: "r"(dst), "l"(src), "r"(valid ? 16 : 0));
}
#define CP_COMMIT() asm volatile("cp.async.commit_group;" ::: "memory")
#define CP_WAIT2()  asm volatile("cp.async.wait_group 2;" ::: "memory")
#define CP_WAIT1()  asm volatile("cp.async.wait_group 1;" ::: "memory")
#define CP_WAIT0()  asm volatile("cp.async.wait_group 0;" ::: "memory")

// ---------------- prep: x->fp16, weights transposed fp16, deg zero, dtype probe ----------------
#define NPREPX (NN * D / 4)
#define NPREPW (7 * 65536 + D * DOUT)
#define NPREP  (NPREPX + NPREPW + NN)
__global__ void k_prep(const float* __restrict__ x,
                       const float* __restrict__ wl, const float* __restrict__ wr,
                       const float* __restrict__ w1, const float* __restrict__ w2,
                       const int* __restrict__ ei32) {
    int idx = blockIdx.x * blockDim.x + threadIdx.x;
    if (blockIdx.x == 0) {   // dtype probe: 256 index pairs (int64 => odd words zero)
        __shared__ int nz;
        if (threadIdx.x == 0) nz = 0;
        __syncthreads();
        if (ei32[2 * threadIdx.x + 1] != 0) atomicOr(&nz, 1);
        __syncthreads();
        if (threadIdx.x == 0) g_is64 = nz ? 0 : 1;
    }
    if (idx < NPREPX) {
        int i = idx * 4;
#pragma unroll
        for (int j = 0; j < 4; j++)
            g_x16[i + j] = __half_as_ushort(__float2half_rn(x[i + j]));
    } else if (idx < NPREPX + 7 * 65536) {
        int q = idx - NPREPX;
        int m = q >> 16, t = q & 65535;
        const float* src = (m < 3) ? (wl + (size_t)m * 65536)
                         : (m < 6) ? (wr + (size_t)(m - 3) * 65536) : w1;
        int k = t >> 8, n = t & 255;
        g_wt[m * 65536 + n * 256 + k] = __half_as_ushort(__float2half_rn(src[t]));
    } else if (idx < NPREPX + NPREPW) {
        int t = idx - NPREPX - 7 * 65536;
        int k = t >> 7, n = t & 127;
        g_wt[7 * 65536 + n * 256 + k] = __half_as_ushort(__float2half_rn(w2[t]));
    } else if (idx < NPREP) {
        g_deg[idx - NPREPX - NPREPW] = 0;
    }
}

// ---------------- CSR build ----------------
__global__ void k_hist(const void* __restrict__ ei) {
    int e = blockIdx.x * blockDim.x + threadIdx.x;
    if (e < NE) {
        unsigned d = (unsigned)edge_at(ei, NE + e);
        if (d < NN) atomicAdd(&g_deg[d], 1);
    }
}
__global__ void k_scan1() {
    __shared__ int s[1024];
    int t = threadIdx.x;
    int i = blockIdx.x * 1024 + t;
    int v = (i < NN) ? g_deg[i] : 0;
    s[t] = v;
    __syncthreads();
    for (int o = 1; o < 1024; o <<= 1) {
        int a = (t >= o) ? s[t - o] : 0;
        __syncthreads();
        s[t] += a;
        __syncthreads();
    }
    if (i < NN) g_rowptr[i] = s[t] - v;
    if (t == 1023) g_bsum[blockIdx.x] = s[1023];
}
// scan3 with inline block-sum prefix (replaces serial scan2)
__global__ void k_scan3() {
    int i = blockIdx.x * blockDim.x + threadIdx.x;
    if (i < NN) {
        int nb = i >> 10;
        int pre = 0;
        for (int b = 0; b < nb; b++) pre += g_bsum[b];
        int rp = g_rowptr[i] + pre;
        g_rowptr[i] = rp;
        g_cursor[i] = rp;
        int dg = g_deg[i];
        g_deginv[i] = 1.0f / (float)(dg > 0 ? dg : 1);
    }
    if (i == 0) g_rowptr[NN] = NE;
}
__global__ void k_fill(const void* __restrict__ ei) {
    int e = blockIdx.x * blockDim.x + threadIdx.x;
    if (e < NE) {
        unsigned d = (unsigned)edge_at(ei, NE + e);
        unsigned s = (unsigned)edge_at(ei, e);
        if (d < NN && s < NN) {
            int pos = atomicAdd(&g_cursor[d], 1);
            g_col[pos] = (int)s;
        }
    }
}

// ---------------- mean aggregation (fp16 half2, smem-staged indices) ----------------
__global__ void k_agg(int src_id) {
    const unsigned int* __restrict__ H = (const unsigned int*)bufp(src_id);
    unsigned int* __restrict__ O = (unsigned int*)g_agg;
    __shared__ int sc[128];
    int t = threadIdx.x;
    for (int r = blockIdx.x; r < NN; r += gridDim.x) {
        int beg = g_rowptr[r], end = g_rowptr[r + 1];
        float a0 = 0.f, a1 = 0.f;
        for (int base = beg; base < end; base += 128) {
            int cnt = min(128, end - base);
            __syncthreads();
            if (t < cnt) sc[t] = g_col[base + t];
            __syncthreads();
            int i = 0;
            for (; i + 4 <= cnt; i += 4) {
                unsigned int v0 = H[(size_t)sc[i]     * 128 + t];
                unsigned int v1 = H[(size_t)sc[i + 1] * 128 + t];
                unsigned int v2 = H[(size_t)sc[i + 2] * 128 + t];
                unsigned int v3 = H[(size_t)sc[i + 3] * 128 + t];
                float2 f0 = __half22float2(*reinterpret_cast<__half2*>(&v0));
                float2 f1 = __half22float2(*reinterpret_cast<__half2*>(&v1));
                float2 f2 = __half22float2(*reinterpret_cast<__half2*>(&v2));
                float2 f3 = __half22float2(*reinterpret_cast<__half2*>(&v3));
                a0 += (f0.x + f1.x) + (f2.x + f3.x);
                a1 += (f0.y + f1.y) + (f2.y + f3.y);
            }
            for (; i < cnt; i++) {
                unsigned int v = H[(size_t)sc[i] * 128 + t];
                float2 f = __half22float2(*reinterpret_cast<__half2*>(&v));
                a0 += f.x;
                a1 += f.y;
            }
        }
        float di = g_deginv[r];
        __half2 o = __floats2half2_rn(a0 * di, a1 * di);
        O[(size_t)r * 128 + t] = *reinterpret_cast<unsigned int*>(&o);
    }
}

// ---------------- fp16 tensor-core GEMM (layers), 3-stage cp.async, K-chunk 32 ----------------
#define TROWB   80
#define TILE_B  (128 * TROWB)       // 10240
#define STAGE_B (2 * TILE_B)        // 20480
#define SMEM_MMA (3 * STAGE_B)      // 61440 (3 stages)

__global__ __launch_bounds__(256, 2)
void k_mma(int a1id, int a2id, int outp, int woff1, int woff2,
           const float* __restrict__ bias) {
    extern __shared__ __align__(16) unsigned char sT[];
    uint32_t sb = smem_u32(sT);
    int tid = threadIdx.x;
    int lane = tid & 31;
    int wid = tid >> 5;
    int wm = wid & 1;
    int wn = wid >> 1;
    int bm = blockIdx.x * 128;
    int bn = blockIdx.y * 128;

    const unsigned short* pA[2] = { bufp(a1id), bufp(a2id) };
    const unsigned short* pB[2] = { g_wt + woff1, g_wt + woff2 };

    float acc[16][4];
#pragma unroll
    for (int i = 0; i < 16; i++)
#pragma unroll
        for (int j = 0; j < 4; j++) acc[i][j] = 0.f;

    int lrow = tid >> 1, s0 = tid & 1;
    int gr = bm + lrow;
    int av = gr < NN;
    size_t arow = (size_t)(av ? gr : 0) * D;
    size_t brow = (size_t)(bn + lrow) * D;
    uint32_t drow = sb + (uint32_t)(lrow * TROWB);

    int grp = lane >> 3, lr = lane & 7;
    int a_r = wm * 64 + ((grp & 1) << 3) + lr;
    int a_c = (grp & 2) ? 8 : 0;
    int b_r = wn * 32 + ((grp & 2) << 2) + lr;
    int b_c = (grp & 1) << 3;
    uint32_t offA = (uint32_t)(a_r * TROWB + a_c * 2);
    uint32_t offB = (uint32_t)(b_r * TROWB + b_c * 2);

    const int NIT = 16;   // dual source, 8 K-chunks each

    // prologue: iterations 0,1 -> stages 0,1
#pragma unroll
    for (int j = 0; j < 2; j++) {
        int s = 0, kc = j;   // j < 8 always here
        uint32_t stg = (uint32_t)(j * STAGE_B);
#pragma unroll
        for (int j2 = 0; j2 < 2; j2++) {
            int seg = s0 + 2 * j2;
            uint32_t d = drow + stg + (uint32_t)(seg * 16);
            size_t go = (size_t)(kc * 32 + seg * 8);
            cpa16(d,          pA[s] + arow + go, av);
            cpa16(d + TILE_B, pB[s] + brow + go, 1);
        }
        CP_COMMIT();
    }

    int stq = 2;             // stage to fill next (rotates 0,1,2)
    int stc = 0;             // stage to compute
    for (int it = 0; it < NIT; it++) {
        // prefetch it+2 into stage stq (its prior user finished at it-1's end sync)
        if (it + 2 < NIT) {
            int j = it + 2;
            int s = j >> 3, kc = j & 7;
            uint32_t stg = (uint32_t)(stq * STAGE_B);
#pragma unroll
            for (int j2 = 0; j2 < 2; j2++) {
                int seg = s0 + 2 * j2;
                uint32_t d = drow + stg + (uint32_t)(seg * 16);
                size_t go = (size_t)(kc * 32 + seg * 8);
                cpa16(d,          pA[s] + arow + go, av);
                cpa16(d + TILE_B, pB[s] + brow + go, 1);
            }
        }
        CP_COMMIT();         // always commit (possibly empty) so WAIT2 is exact
        CP_WAIT2();          // stage stc ready; it+1, it+2 in flight
        __syncthreads();

        uint32_t base = sb + (uint32_t)(stc * STAGE_B);
#pragma unroll
        for (int kk = 0; kk < 32; kk += 16) {
            uint32_t koff = (uint32_t)(kk * 2);
            uint32_t b[4][2];
#pragma unroll
            for (int nb = 0; nb < 2; nb++) {
                uint32_t off = offB + koff + (uint32_t)(nb * 16 * TROWB);
                uint32_t t0, t1, t2, t3;
                ldm4(base + TILE_B + off, t0, t1, t2, t3);
                b[nb * 2][0] = t0; b[nb * 2][1] = t1;
                b[nb * 2 + 1][0] = t2; b[nb * 2 + 1][1] = t3;
            }
            uint32_t a[4];
#pragma unroll
            for (int mi = 0; mi < 4; mi++) {
                uint32_t off = offA + koff + (uint32_t)(mi * 16 * TROWB);
                ldm4(base + off, a[0], a[1], a[2], a[3]);
#pragma unroll
                for (int nj = 0; nj < 4; nj++)
                    mma16816(acc[mi * 4 + nj], a, b[nj]);
            }
        }
        __syncthreads();     // protect stage stc: it becomes stq at it+1
        stq = stc;
        stc = (stc + 1 == 3) ? 0 : stc + 1;
    }

    unsigned short* oH = bufp(outp);
#pragma unroll
    for (int mi = 0; mi < 4; mi++) {
#pragma unroll
        for (int nj = 0; nj < 4; nj++) {
            float* c = acc[mi * 4 + nj];
            int col = bn + wn * 32 + nj * 8 + (lane & 3) * 2;
            float bi0 = bias[col], bi1 = bias[col + 1];
#pragma unroll
            for (int half = 0; half < 2; half++) {
                int r = bm + wm * 64 + mi * 16 + (lane >> 2) + half * 8;
                if (r >= NN) continue;
                float v0 = fmaxf(c[half * 2] + bi0, 0.f);
                float v1 = fmaxf(c[half * 2 + 1] + bi1, 0.f);
                *(ushort2*)(oH + (size_t)r * D + col) = make_ushort2(
                    __half_as_ushort(__float2half_rn(v0)),
                    __half_as_ushort(__float2half_rn(v1)));
            }
        }
    }
}

// ---------------- fused post-MLP: out = log_softmax((h0@w1+b1)@w2+b2) ----------------
#define ZROWB 528
#define Z_OFF (2 * STAGE_B)                  // 40960 (k_post uses 2-stage pipeline)
#define SMEM_POST (Z_OFF + 128 * ZROWB)      // 108544

__global__ __launch_bounds__(256, 2)
void k_post(float* __restrict__ out, const float* __restrict__ b1v,
            const float* __restrict__ b2v) {
    extern __shared__ __align__(16) unsigned char sT[];
    uint32_t sb = smem_u32(sT);
    uint32_t zb = sb + Z_OFF;
    int tid = threadIdx.x, lane = tid & 31, wid = tid >> 5;
    int wm = wid & 1, wn = wid >> 1;
    int bm = blockIdx.x * 128;

    const unsigned short* A1 = g_h0;
    const unsigned short* B1 = g_wt + 6 * 65536;
    const unsigned short* B2 = g_wt + 7 * 65536;

    int lrow = tid >> 1, s0 = tid & 1;
    int gr = bm + lrow;
    int av = gr < NN;
    size_t arow = (size_t)(av ? gr : 0) * D;
    uint32_t drow = sb + (uint32_t)(lrow * TROWB);

    int grp = lane >> 3, lr = lane & 7;
    int a_r = wm * 64 + ((grp & 1) << 3) + lr;
    int a_c = (grp & 2) ? 8 : 0;
    int b_r = wn * 32 + ((grp & 2) << 2) + lr;
    int b_c = (grp & 1) << 3;
    uint32_t offA = (uint32_t)(a_r * TROWB + a_c * 2);
    uint32_t offB = (uint32_t)(b_r * TROWB + b_c * 2);

    // ---- GEMM1: z[128 x 256] = h0 @ w1T + b1 (two 128-col passes)
    for (int pn = 0; pn < 2; pn++) {
        int bn = pn * 128;
        size_t brow = (size_t)(bn + lrow) * D;
        float acc[16][4];
#pragma unroll
        for (int i = 0; i < 16; i++)
#pragma unroll
            for (int j = 0; j < 4; j++) acc[i][j] = 0.f;

#pragma unroll
        for (int j2 = 0; j2 < 2; j2++) {
            int seg = s0 + 2 * j2;
            uint32_t d = drow + (uint32_t)(seg * 16);
            size_t go = (size_t)(seg * 8);
            cpa16(d,          A1 + arow + go, av);
            cpa16(d + TILE_B, B1 + brow + go, 1);
        }
        CP_COMMIT();

        for (int it = 0; it < 8; it++) {
            if (it + 1 < 8) {
                int kc = it + 1;
                uint32_t stg = (uint32_t)(((it + 1) & 1) * STAGE_B);
#pragma unroll
                for (int j2 = 0; j2 < 2; j2++) {
                    int seg = s0 + 2 * j2;
                    uint32_t d = drow + stg + (uint32_t)(seg * 16);
                    size_t go = (size_t)(kc * 32 + seg * 8);
                    cpa16(d,          A1 + arow + go, av);
                    cpa16(d + TILE_B, B1 + brow + go, 1);
                }
                CP_COMMIT();
                CP_WAIT1();
            } else {
                CP_WAIT0();
            }
            __syncthreads();

            uint32_t base = sb + (uint32_t)((it & 1) * STAGE_B);
#pragma unroll
            for (int kk = 0; kk < 32; kk += 16) {
                uint32_t koff = (uint32_t)(kk * 2);
                uint32_t b[4][2];
#pragma unroll
                for (int nb = 0; nb < 2; nb++) {
                    uint32_t off = offB + koff + (uint32_t)(nb * 16 * TROWB);
                    uint32_t t0, t1, t2, t3;
                    ldm4(base + TILE_B + off, t0, t1, t2, t3);
                    b[nb * 2][0] = t0; b[nb * 2][1] = t1;
                    b[nb * 2 + 1][0] = t2; b[nb * 2 + 1][1] = t3;
                }
                uint32_t a[4];
#pragma unroll
                for (int mi = 0; mi < 4; mi++) {
                    uint32_t off = offA + koff + (uint32_t)(mi * 16 * TROWB);
                    ldm4(base + off, a[0], a[1], a[2], a[3]);
#pragma unroll
                    for (int nj = 0; nj < 4; nj++)
                        mma16816(acc[mi * 4 + nj], a, b[nj]);
                }
            }
            __syncthreads();
        }

        // epilogue -> z smem (fp16, +b1, no relu)
#pragma unroll
        for (int mi = 0; mi < 4; mi++) {
#pragma unroll
            for (int nj = 0; nj < 4; nj++) {
                float* c = acc[mi * 4 + nj];
                int col = bn + wn * 32 + nj * 8 + (lane & 3) * 2;
                float bi0 = b1v[col], bi1 = b1v[col + 1];
#pragma unroll
                for (int half = 0; half < 2; half++) {
                    int rl = wm * 64 + mi * 16 + (lane >> 2) + half * 8;
                    __half2 o = __floats2half2_rn(c[half * 2] + bi0,
                                                  c[half * 2 + 1] + bi1);
                    *(__half2*)(sT + Z_OFF + rl * ZROWB + col * 2) = o;
                }
            }
        }
    }
    __syncthreads();   // z complete

    // ---- GEMM2: o[128 x 128] = z @ w2T (+b2 later)
    float acc[16][4];
#pragma unroll
    for (int i = 0; i < 16; i++)
#pragma unroll
        for (int j = 0; j < 4; j++) acc[i][j] = 0.f;

    size_t brow2 = (size_t)lrow * D;
#pragma unroll
    for (int j2 = 0; j2 < 2; j2++) {
        int seg = s0 + 2 * j2;
        cpa16(drow + (uint32_t)(seg * 16), B2 + brow2 + (size_t)(seg * 8), 1);
    }
    CP_COMMIT();

    uint32_t offA2 = (uint32_t)(a_r * ZROWB + a_c * 2);
    for (int it = 0; it < 8; it++) {
        if (it + 1 < 8) {
            int kc = it + 1;
            uint32_t stg = (uint32_t)(((it + 1) & 1) * STAGE_B);
#pragma unroll
            for (int j2 = 0; j2 < 2; j2++) {
                int seg = s0 + 2 * j2;
                cpa16(drow + stg + (uint32_t)(seg * 16),
                      B2 + brow2 + (size_t)(kc * 32 + seg * 8), 1);
            }
            CP_COMMIT();
            CP_WAIT1();
        } else {
            CP_WAIT0();
        }
        __syncthreads();

        uint32_t base = sb + (uint32_t)((it & 1) * STAGE_B);
#pragma unroll
        for (int kk = 0; kk < 32; kk += 16) {
            uint32_t b[4][2];
#pragma unroll
            for (int nb = 0; nb < 2; nb++) {
                uint32_t off = offB + (uint32_t)(kk * 2) + (uint32_t)(nb * 16 * TROWB);
                uint32_t t0, t1, t2, t3;
                ldm4(base + off, t0, t1, t2, t3);
                b[nb * 2][0] = t0; b[nb * 2][1] = t1;
                b[nb * 2 + 1][0] = t2; b[nb * 2 + 1][1] = t3;
            }
            uint32_t a[4];
#pragma unroll
            for (int mi = 0; mi < 4; mi++) {
                uint32_t off = zb + offA2 + (uint32_t)((it * 32 + kk) * 2)
                             + (uint32_t)(mi * 16 * ZROWB);
                ldm4(off, a[0], a[1], a[2], a[3]);
#pragma unroll
                for (int nj = 0; nj < 4; nj++)
                    mma16816(acc[mi * 4 + nj], a, b[nj]);
            }
        }
        __syncthreads();
    }

    // ---- bias + log_softmax
#pragma unroll
    for (int nj = 0; nj < 4; nj++) {
        int col = wn * 32 + nj * 8 + (lane & 3) * 2;
        float bi0 = b2v[col], bi1 = b2v[col + 1];
#pragma unroll
        for (int mi = 0; mi < 4; mi++) {
            acc[mi * 4 + nj][0] += bi0; acc[mi * 4 + nj][1] += bi1;
            acc[mi * 4 + nj][2] += bi0; acc[mi * 4 + nj][3] += bi1;
        }
    }

    float* redm = (float*)sT;
    float* reds = (float*)sT + 512;
#pragma unroll
    for (int mi = 0; mi < 4; mi++)
#pragma unroll
        for (int half = 0; half < 2; half++) {
            float m = -3.4e38f;
#pragma unroll
            for (int nj = 0; nj < 4; nj++) {
                m = fmaxf(m, acc[mi * 4 + nj][half * 2]);
                m = fmaxf(m, acc[mi * 4 + nj][half * 2 + 1]);
            }
            m = fmaxf(m, __shfl_xor_sync(0xffffffffu, m, 1));
            m = fmaxf(m, __shfl_xor_sync(0xffffffffu, m, 2));
            int rl = wm * 64 + mi * 16 + (lane >> 2) + half * 8;
            if ((lane & 3) == 0) redm[rl * 4 + wn] = m;
        }
    __syncthreads();
    float mm8[8];
#pragma unroll
    for (int mi = 0; mi < 4; mi++)
#pragma unroll
        for (int half = 0; half < 2; half++) {
            int rl = wm * 64 + mi * 16 + (lane >> 2) + half * 8;
            mm8[mi * 2 + half] = fmaxf(fmaxf(redm[rl * 4], redm[rl * 4 + 1]),
                                       fmaxf(redm[rl * 4 + 2], redm[rl * 4 + 3]));
        }
#pragma unroll
    for (int mi = 0; mi < 4; mi++)
#pragma unroll
        for (int half = 0; half < 2; half++) {
            float mm = mm8[mi * 2 + half];
            float s = 0.f;
#pragma unroll
            for (int nj = 0; nj < 4; nj++) {
                s += expf(acc[mi * 4 + nj][half * 2] - mm);
                s += expf(acc[mi * 4 + nj][half * 2 + 1] - mm);
            }
            s += __shfl_xor_sync(0xffffffffu, s, 1);
            s += __shfl_xor_sync(0xffffffffu, s, 2);
            int rl = wm * 64 + mi * 16 + (lane >> 2) + half * 8;
            if ((lane & 3) == 0) reds[rl * 4 + wn] = s;
        }
    __syncthreads();
#pragma unroll
    for (int mi = 0; mi < 4; mi++)
#pragma unroll
        for (int half = 0; half < 2; half++) {
            int rl = wm * 64 + mi * 16 + (lane >> 2) + half * 8;
            int r = bm + rl;
            if (r >= NN) continue;
            float tot = reds[rl * 4] + reds[rl * 4 + 1] + reds[rl * 4 + 2] + reds[rl * 4 + 3];
            float sub = mm8[mi * 2 + half] + logf(tot);
#pragma unroll
            for (int nj = 0; nj < 4; nj++) {
                int col = wn * 32 + nj * 8 + (lane & 3) * 2;
                float2 v = make_float2(acc[mi * 4 + nj][half * 2] - sub,
                                       acc[mi * 4 + nj][half * 2 + 1] - sub);
                *(float2*)(out + (size_t)r * DOUT + col) = v;
            }
        }
}

// ---------------- launch: kernel launches ONLY ----------------
extern "C" void kernel_launch(void* const* d_in, const int* in_sizes, int n_in,
                              void* d_out, int out_size) {
    const float* x  = (const float*)d_in[0];
    const void*  ei = d_in[1];
    const float* wl = (const float*)d_in[2];
    const float* bl = (const float*)d_in[3];
    const float* wr = (const float*)d_in[4];
    const float* w1 = (const float*)d_in[5];
    const float* b1 = (const float*)d_in[6];
    const float* w2 = (const float*)d_in[7];
    const float* b2 = (const float*)d_in[8];
    float* out = (float*)d_out;

    cudaFuncSetAttribute(k_mma,  cudaFuncAttributeMaxDynamicSharedMemorySize, SMEM_MMA);
    cudaFuncSetAttribute(k_post, cudaFuncAttributeMaxDynamicSharedMemorySize, SMEM_POST);

    // prep (x16 + weights + deg zero + dtype probe), then CSR by dst
    k_prep<<<(NPREP + 255) / 256, 256>>>(x, wl, wr, w1, w2, (const int*)ei);
    k_hist<<<(NE + 255) / 256, 256>>>(ei);
    k_scan1<<<SCAN_B, 1024>>>();
    k_scan3<<<(NN + 255) / 256, 256>>>();
    k_fill<<<(NE + 255) / 256, 256>>>(ei);

    dim3 g2((NN + 127) / 128, 2);

    // layer 0: agg(x); h0 = relu(agg@wl0 + x@wr0 + bl0)
    k_agg<<<6144, 128>>>(0);
    k_mma<<<g2, 256, SMEM_MMA>>>(3, 0, 1, 0 * 65536, 3 * 65536, bl + 0 * D);
    // layer 1: agg(h0); h1 = relu(...)
    k_agg<<<6144, 128>>>(1);
    k_mma<<<g2, 256, SMEM_MMA>>>(3, 1, 2, 1 * 65536, 4 * 65536, bl + 1 * D);
    // layer 2: agg(h1); h0 = relu(...)
    k_agg<<<6144, 128>>>(2);
    k_mma<<<g2, 256, SMEM_MMA>>>(3, 2, 1, 2 * 65536, 5 * 65536, bl + 2 * D);
    // fused post_mp + log_softmax
    k_post<<<(NN + 127) / 128, 256, SMEM_POST>>>(out, b1, b2);
}